// round 6
// baseline (speedup 1.0000x reference)
#include <cuda_runtime.h>
#include <cstdint>

#define BATCH 128
#define NAG   64
#define NEDGE 4032
#define DN    16
#define HDIM  64
#define DOUT  16

// ---------------- scratch (no cudaMalloc) ----------------
__device__ float g_A0[BATCH * NAG * HDIM];
__device__ float g_C0[BATCH * NAG * HDIM];
__device__ float g_A1[BATCH * NAG * HDIM];
__device__ float g_C1[BATCH * NAG * HDIM];
__device__ float g_msgT[2 * BATCH * NAG * HDIM];        // per-type messages
__device__ uint32_t g_Bfrag[2 * 64 * 2 * 32 * 2];       // [t][tile(kt*8+nt)][hl][lane][2]

// ---------------- helpers ----------------
__device__ __forceinline__ uint32_t f2tf32(float f) {
    uint32_t u;
    asm("cvt.rna.tf32.f32 %0, %1;" : "=r"(u) : "f"(f));
    return u;
}
__device__ __forceinline__ void mma_tf32(float c[4],
    uint32_t a0, uint32_t a1, uint32_t a2, uint32_t a3,
    uint32_t b0, uint32_t b1)
{
    asm volatile(
        "mma.sync.aligned.m16n8k8.row.col.f32.tf32.tf32.f32 "
        "{%0,%1,%2,%3}, {%4,%5,%6,%7}, {%8,%9}, {%0,%1,%2,%3};"
        : "+f"(c[0]), "+f"(c[1]), "+f"(c[2]), "+f"(c[3])
        : "r"(a0), "r"(a1), "r"(a2), "r"(a3), "r"(b0), "r"(b1));
}

// smem byte offsets for k2 (dynamic)
#define ASTRIDE 68                       /* floats; 68%32==4 -> conflict-free frag reads */
#define AH_OFF  0                        /* 64 x 68 x 4 = 17408 */
#define AL_OFF  17408
#define B_OFF   34816                    /* 32768: [tile][hl][lane][2] u32 */
#define CB_OFF  67584                    /* 64 floats */
#define WT_OFF  67840                    /* 64 floats */
#define B2_OFF  68096                    /* 64 floats */
#define SM_TOT  68352
#define RSTRIDE 65                       /* epilogue R (overlays A region) */

// ---------------- K0: W2 -> tf32 hi/lo fragments ----------------
// b0: (k = kt*8 + lane%4,     n = nt*8 + lane/4)
// b1: (k = kt*8 + lane%4 + 4, n = nt*8 + lane/4)
__global__ __launch_bounds__(64) void k0_bfrag(
    const float* __restrict__ e0w2, const float* __restrict__ e1w2)
{
    int blk  = blockIdx.x;       // 0..127
    int t    = blk >> 6;
    int tile = blk & 63;
    int kt   = tile >> 3, nt = tile & 7;
    int tid  = threadIdx.x;
    int hl   = tid >> 5;
    int lane = tid & 31;

    const float* w2t = t ? e1w2 : e0w2;
    int k0 = kt * 8 + (lane & 3);
    int n  = nt * 8 + (lane >> 2);
    float w0 = w2t[k0 * HDIM + n];
    float w1 = w2t[(k0 + 4) * HDIM + n];

    uint32_t v0, v1;
    if (hl == 0) { v0 = f2tf32(w0); v1 = f2tf32(w1); }
    else {
        uint32_t h0 = f2tf32(w0), h1 = f2tf32(w1);
        v0 = f2tf32(w0 - __uint_as_float(h0));
        v1 = f2tf32(w1 - __uint_as_float(h1));
    }
    uint32_t* dst = g_Bfrag + (((t * 64 + tile) * 2 + hl) * 32 + lane) * 2;
    dst[0] = v0; dst[1] = v1;
}

// ---------------- K1: factored layer-1 terms ----------------
__global__ __launch_bounds__(64) void k1_precompute(
    const float* __restrict__ x,
    const float* __restrict__ e0w1, const float* __restrict__ e0b1,
    const float* __restrict__ e1w1, const float* __restrict__ e1b1)
{
    int bn = blockIdx.x;
    int j  = threadIdx.x;
    __shared__ float xs[DN];
    if (j < DN) xs[j] = x[bn * DN + j];
    __syncthreads();

    float a0 = 0.f, a1 = 0.f, c0 = e0b1[j], c1 = e1b1[j];
#pragma unroll
    for (int i = 0; i < DN; i++) {
        float xv = xs[i];
        a0 += xv * e0w1[i * HDIM + j];
        c0 += xv * e0w1[(DN + i) * HDIM + j];
        a1 += xv * e1w1[i * HDIM + j];
        c1 += xv * e1w1[(DN + i) * HDIM + j];
    }
    g_A0[bn * HDIM + j] = a0;
    g_C0[bn * HDIM + j] = c0;
    g_A1[bn * HDIM + j] = a1;
    g_C1[bn * HDIM + j] = c1;
}

// ---------------- K2: 3xTF32 mma.sync GEMM per (b, type, recv) ----------------
// H[64s x 64k] = relu(A_t[b,s,:] + C_t[b,r,:]);  D = H @ W2_t  (64x64)
// msg_t[b,r,j] = sum_s wt[s] * relu(D[s,j] + b2[j])
__global__ __launch_bounds__(128) void k2_mma(
    const float* __restrict__ etypes,
    const float* __restrict__ e0b2, const float* __restrict__ e1b2)
{
    extern __shared__ __align__(16) char smem[];

    int blk = blockIdx.x;            // grid = BATCH*2*64
    int r   = blk & 63;
    int t   = (blk >> 6) & 1;
    int b   = blk >> 7;
    int tid = threadIdx.x;
    int w   = tid >> 5;              // warp = m-tile (16 senders)
    int lane = tid & 31;
    int g4  = lane >> 2;             // groupID
    int t4  = lane & 3;              // threadID_in_group

    const float* At = (t ? g_A1 : g_A0) + (long)(b * NAG) * HDIM;
    const float* Ct = (t ? g_C1 : g_C0) + (long)(b * NAG) * HDIM;
    const float* b2t = t ? e1b2 : e0b2;

    float* cbuf = (float*)(smem + CB_OFF);
    float* wts  = (float*)(smem + WT_OFF);
    float* b2s  = (float*)(smem + B2_OFF);

    // ---- small loads ----
    if (tid < 64) {
        cbuf[tid] = Ct[r * HDIM + tid];
        int s = tid;
        float wt = 0.f;
        if (s != r) {
            int e = s * 63 + r - (r > s ? 1 : 0);   // np.where(ones-eye) ordering
            wt = etypes[((long)b * NEDGE + e) * 3 + 1 + t];
        }
        wts[s] = wt;
    } else {
        b2s[tid - 64] = b2t[tid - 64];
    }
    __syncthreads();

    // ---- build A hi/lo (64 x 64 tf32, row stride 68) ----
    {
        const float4* A4 = (const float4*)At;
        const float4* C4 = (const float4*)cbuf;
#pragma unroll
        for (int it = 0; it < 8; it++) {
            int idx = it * 128 + tid;        // 1024 float4
            int m = idx >> 4, k4 = idx & 15;
            float4 a = A4[m * 16 + k4];
            float4 c = C4[k4];
            float hx = fmaxf(a.x + c.x, 0.f), hy = fmaxf(a.y + c.y, 0.f);
            float hz = fmaxf(a.z + c.z, 0.f), hw = fmaxf(a.w + c.w, 0.f);
            uint4 hi, lo;
            hi.x = f2tf32(hx); lo.x = f2tf32(hx - __uint_as_float(hi.x));
            hi.y = f2tf32(hy); lo.y = f2tf32(hy - __uint_as_float(hi.y));
            hi.z = f2tf32(hz); lo.z = f2tf32(hz - __uint_as_float(hi.z));
            hi.w = f2tf32(hw); lo.w = f2tf32(hw - __uint_as_float(hi.w));
            uint32_t o = m * (ASTRIDE * 4) + k4 * 16;
            *(uint4*)(smem + AH_OFF + o) = hi;
            *(uint4*)(smem + AL_OFF + o) = lo;
        }
    }
    // ---- copy B fragments for this type (32 KB, L1-hot) ----
    {
        const float4* src = (const float4*)(g_Bfrag + (long)t * 8192);
        float4* dst = (float4*)(smem + B_OFF);
#pragma unroll
        for (int it = 0; it < 16; it++)
            dst[it * 128 + tid] = src[it * 128 + tid];
    }
    __syncthreads();

    // ---- 3xTF32 main loop: C[nt][4] accumulates HH + HL + LH ----
    float C[8][4];
#pragma unroll
    for (int nt = 0; nt < 8; nt++)
#pragma unroll
        for (int i = 0; i < 4; i++) C[nt][i] = 0.f;

    const uint32_t* Bu = (const uint32_t*)(smem + B_OFF);

#pragma unroll
    for (int split = 0; split < 3; split++) {
        const char* Ab = smem + ((split == 2) ? AL_OFF : AH_OFF);
        int bh = (split == 1) ? 1 : 0;
#pragma unroll
        for (int kt = 0; kt < 8; kt++) {
            int row0 = w * 16 + g4;
            int col0 = kt * 8 + t4;
            const float* Af = (const float*)Ab;
            uint32_t a0 = __float_as_uint(Af[row0 * ASTRIDE + col0]);
            uint32_t a1 = __float_as_uint(Af[(row0 + 8) * ASTRIDE + col0]);
            uint32_t a2 = __float_as_uint(Af[row0 * ASTRIDE + col0 + 4]);
            uint32_t a3 = __float_as_uint(Af[(row0 + 8) * ASTRIDE + col0 + 4]);
#pragma unroll
            for (int nt = 0; nt < 8; nt++) {
                const uint32_t* bp = Bu + (((kt * 8 + nt) * 2 + bh) * 32 + lane) * 2;
                uint2 bv = *(const uint2*)bp;
                mma_tf32(C[nt], a0, a1, a2, a3, bv.x, bv.y);
            }
        }
    }

    // ---- epilogue: relu+bias, weight, stage to R (overlays A region) ----
    __syncthreads();                    // everyone done reading A
    float* R = (float*)smem;            // R[64][65]
    {
        int row0 = w * 16 + g4;
        float wt0 = wts[row0], wt1 = wts[row0 + 8];
#pragma unroll
        for (int nt = 0; nt < 8; nt++) {
            int col = nt * 8 + 2 * t4;
            float bA = b2s[col], bB = b2s[col + 1];
            R[row0 * RSTRIDE + col]           = wt0 * fmaxf(C[nt][0] + bA, 0.f);
            R[row0 * RSTRIDE + col + 1]       = wt0 * fmaxf(C[nt][1] + bB, 0.f);
            R[(row0 + 8) * RSTRIDE + col]     = wt1 * fmaxf(C[nt][2] + bA, 0.f);
            R[(row0 + 8) * RSTRIDE + col + 1] = wt1 * fmaxf(C[nt][3] + bB, 0.f);
        }
    }
    __syncthreads();

    // ---- reduce over senders ----
    if (tid < 64) {
        int j = tid;
        float acc = 0.f;
#pragma unroll
        for (int s = 0; s < NAG; s++)
            acc += R[s * RSTRIDE + j];
        g_msgT[(((long)t * BATCH + b) * NAG + r) * HDIM + j] = acc;
    }
}

// ---------------- K3: node decoder ----------------
__global__ __launch_bounds__(64) void k3_decode(
    const float* __restrict__ x,
    const float* __restrict__ ndw1, const float* __restrict__ ndb1,
    const float* __restrict__ ndw2, const float* __restrict__ ndb2,
    float* __restrict__ out)
{
    int bn = blockIdx.x;
    int j  = threadIdx.x;
    __shared__ float xs[DN];
    __shared__ float ms[HDIM];
    __shared__ float hs[HDIM];

    if (j < DN) xs[j] = x[bn * DN + j];
    ms[j] = g_msgT[(long)bn * HDIM + j] +
            g_msgT[(long)(BATCH * NAG + bn) * HDIM + j];
    __syncthreads();

    float h = ndb1[j];
#pragma unroll
    for (int i = 0; i < DN; i++)   h = fmaf(xs[i], ndw1[i * HDIM + j], h);
#pragma unroll
    for (int k = 0; k < HDIM; k++) h = fmaf(ms[k], ndw1[(DN + k) * HDIM + j], h);
    hs[j] = fmaxf(h, 0.f);
    __syncthreads();

    if (j < DOUT) {
        float o = ndb2[j];
#pragma unroll
        for (int k = 0; k < HDIM; k++) o = fmaf(hs[k], ndw2[k * DOUT + j], o);
        out[bn * DOUT + j] = fmaxf(o, 0.f);
    }
}

extern "C" void kernel_launch(void* const* d_in, const int* in_sizes, int n_in,
                              void* d_out, int out_size)
{
    const float* node_states = (const float*)d_in[0];
    const float* edge_types  = (const float*)d_in[1];
    const float* e0_w1 = (const float*)d_in[2];
    const float* e0_b1 = (const float*)d_in[3];
    const float* e0_w2 = (const float*)d_in[4];
    const float* e0_b2 = (const float*)d_in[5];
    const float* e1_w1 = (const float*)d_in[6];
    const float* e1_b1 = (const float*)d_in[7];
    const float* e1_w2 = (const float*)d_in[8];
    const float* e1_b2 = (const float*)d_in[9];
    const float* nd_w1 = (const float*)d_in[10];
    const float* nd_b1 = (const float*)d_in[11];
    const float* nd_w2 = (const float*)d_in[12];
    const float* nd_b2 = (const float*)d_in[13];
    float* out = (float*)d_out;

    static int smem_set = 0;
    if (!smem_set) {
        cudaFuncSetAttribute(k2_mma, cudaFuncAttributeMaxDynamicSharedMemorySize, SM_TOT);
        smem_set = 1;
    }

    k0_bfrag<<<128, 64>>>(e0_w2, e1_w2);
    k1_precompute<<<BATCH * NAG, 64>>>(node_states, e0_w1, e0_b1, e1_w1, e1_b1);
    k2_mma<<<BATCH * 2 * NAG, 128, SM_TOT>>>(edge_types, e0_b2, e1_b2);
    k3_decode<<<BATCH * NAG, 64>>>(node_states, nd_w1, nd_b1, nd_w2, nd_b2, out);
}

// round 7
// speedup vs baseline: 1.0916x; 1.0916x over previous
#include <cuda_runtime.h>
#include <cstdint>

#define BATCH 128
#define NAG   64
#define NEDGE 4032
#define DN    16
#define HDIM  64
#define DOUT  16

// ---------------- scratch (no cudaMalloc) ----------------
__device__ float g_A0[BATCH * NAG * HDIM];
__device__ float g_C0[BATCH * NAG * HDIM];
__device__ float g_A1[BATCH * NAG * HDIM];
__device__ float g_C1[BATCH * NAG * HDIM];
__device__ float g_msgT[2 * BATCH * NAG * HDIM];       // per-type messages
// B fragments: [t][kt(4)][nt(8)][hl(2)][lane(32)][2] u32 (bf16x2)
__device__ uint32_t g_Bb[2 * 4 * 8 * 2 * 32 * 2];

// ---------------- helpers ----------------
// pack two floats -> bf16x2, low half = first (lower-k) element
__device__ __forceinline__ uint32_t pkbf(float lok, float hik) {
    uint32_t d;
    asm("cvt.rn.bf16x2.f32 %0, %1, %2;" : "=r"(d) : "f"(hik), "f"(lok));
    return d;
}
__device__ __forceinline__ float bf_lo(uint32_t u) { return __uint_as_float(u << 16); }
__device__ __forceinline__ float bf_hi(uint32_t u) { return __uint_as_float(u & 0xffff0000u); }

__device__ __forceinline__ void mma_bf16(float c[4],
    uint32_t a0, uint32_t a1, uint32_t a2, uint32_t a3,
    uint32_t b0, uint32_t b1)
{
    asm volatile(
        "mma.sync.aligned.m16n8k16.row.col.f32.bf16.bf16.f32 "
        "{%0,%1,%2,%3}, {%4,%5,%6,%7}, {%8,%9}, {%0,%1,%2,%3};"
        : "+f"(c[0]), "+f"(c[1]), "+f"(c[2]), "+f"(c[3])
        : "r"(a0), "r"(a1), "r"(a2), "r"(a3), "r"(b0), "r"(b1));
}

// smem layout (bytes); A word-stride 36 -> A-frag bank = 4*g4+t4 (perm of 0..31)
#define AHW     36
#define AH_OFF  0                         /* 2 recv * 64 * 36 u32 = 18432 B */
#define AL_OFF  18432
#define B_OFF   36864                     /* 4096 u32 = 16384 B */
#define CB_OFF  53248                     /* 2*64 floats */
#define WT_OFF  53760                     /* 2*64 floats */
#define B2_OFF  54272                     /* 64 floats */
#define SM_TOT  54528
#define RSTRIDE 65                        /* epilogue R overlays A region */

// ---------------- K0: W2 -> bf16 hi/lo fragments ----------------
__global__ __launch_bounds__(64) void k0_bfrag(
    const float* __restrict__ e0w2, const float* __restrict__ e1w2)
{
    int blk = blockIdx.x;                 // 0..63 : t*32 + kt*8 + nt
    int t   = blk >> 5;
    int kt  = (blk >> 3) & 3;
    int nt  = blk & 7;
    int tid = threadIdx.x;
    int hl  = tid >> 5;
    int lane = tid & 31;
    int g4  = lane >> 2, t4 = lane & 3;

    const float* w2t = t ? e1w2 : e0w2;
    int n  = nt * 8 + g4;
    int k0 = kt * 16 + 2 * t4;
    float w00 = w2t[k0 * HDIM + n];
    float w01 = w2t[(k0 + 1) * HDIM + n];
    float w08 = w2t[(k0 + 8) * HDIM + n];
    float w09 = w2t[(k0 + 9) * HDIM + n];

    uint32_t H0 = pkbf(w00, w01), H1 = pkbf(w08, w09);
    uint32_t v0, v1;
    if (hl == 0) { v0 = H0; v1 = H1; }
    else {
        v0 = pkbf(w00 - bf_lo(H0), w01 - bf_hi(H0));
        v1 = pkbf(w08 - bf_lo(H1), w09 - bf_hi(H1));
    }
    uint32_t* dst = g_Bb + ((((t * 4 + kt) * 8 + nt) * 2 + hl) * 32 + lane) * 2;
    dst[0] = v0; dst[1] = v1;
}

// ---------------- K1: factored layer-1 terms ----------------
__global__ __launch_bounds__(64) void k1_precompute(
    const float* __restrict__ x,
    const float* __restrict__ e0w1, const float* __restrict__ e0b1,
    const float* __restrict__ e1w1, const float* __restrict__ e1b1)
{
    int bn = blockIdx.x;
    int j  = threadIdx.x;
    __shared__ float xs[DN];
    if (j < DN) xs[j] = x[bn * DN + j];
    __syncthreads();

    float a0 = 0.f, a1 = 0.f, c0 = e0b1[j], c1 = e1b1[j];
#pragma unroll
    for (int i = 0; i < DN; i++) {
        float xv = xs[i];
        a0 += xv * e0w1[i * HDIM + j];
        c0 += xv * e0w1[(DN + i) * HDIM + j];
        a1 += xv * e1w1[i * HDIM + j];
        c1 += xv * e1w1[(DN + i) * HDIM + j];
    }
    g_A0[bn * HDIM + j] = a0;
    g_C0[bn * HDIM + j] = c0;
    g_A1[bn * HDIM + j] = a1;
    g_C1[bn * HDIM + j] = c1;
}

// ---------------- K2: 3x-split bf16 mma.sync per (b, type, recv-pair) ----------------
// 256 threads = 8 warps: warp w -> receiver rl = w>>2, m-tile = w&3.
__global__ __launch_bounds__(256) void k2_mma(
    const float* __restrict__ etypes,
    const float* __restrict__ e0b2, const float* __restrict__ e1b2)
{
    extern __shared__ __align__(16) char smem[];

    int blk = blockIdx.x;                 // grid = BATCH * 2 * 32
    int rp  = blk & 31;
    int t   = (blk >> 5) & 1;
    int b   = blk >> 6;
    int tid = threadIdx.x;
    int w   = tid >> 5;
    int lane = tid & 31;
    int g4  = lane >> 2, t4 = lane & 3;

    const float* At  = (t ? g_A1 : g_A0) + (long)(b * NAG) * HDIM;
    const float* Ct  = (t ? g_C1 : g_C0) + (long)(b * NAG) * HDIM;
    const float* b2t = t ? e1b2 : e0b2;

    uint32_t* Ahw = (uint32_t*)(smem + AH_OFF);
    uint32_t* Alw = (uint32_t*)(smem + AL_OFF);
    uint32_t* Bs  = (uint32_t*)(smem + B_OFF);
    float* cbuf = (float*)(smem + CB_OFF);
    float* wts  = (float*)(smem + WT_OFF);
    float* b2s  = (float*)(smem + B2_OFF);

    // ---- small loads: C rows (2 recv), edge weights, bias ----
    if (tid < 128) {
        int rl = tid >> 6, k = tid & 63;
        int r  = rp * 2 + rl;
        cbuf[rl * 64 + k] = Ct[r * HDIM + k];
        int s = k;
        float wt = 0.f;
        if (s != r) {
            int e = s * 63 + r - (r > s ? 1 : 0);   // np.where(ones-eye) ordering
            wt = etypes[((long)b * NEDGE + e) * 3 + 1 + t];
        }
        wts[rl * 64 + s] = wt;
    } else if (tid < 192) {
        b2s[tid - 128] = b2t[tid - 128];
    }
    // ---- copy B fragments for this type (16 KB) ----
    {
        const float4* src = (const float4*)(g_Bb + (long)t * 4096);
        float4* dst = (float4*)Bs;
#pragma unroll
        for (int it = 0; it < 4; it++)
            dst[it * 256 + tid] = src[it * 256 + tid];
    }
    __syncthreads();

    // ---- build A hi/lo bf16x2 tiles for both receivers ----
    {
        const float4* A4 = (const float4*)At;
        const float4* C4 = (const float4*)cbuf;
#pragma unroll
        for (int it = 0; it < 8; it++) {
            int idx = it * 256 + tid;      // 2048 float4: recv(1) x m(6) x k4(4)
            int recv = idx >> 10;
            int rem  = idx & 1023;
            int m = rem >> 4, k4 = rem & 15;
            float4 a = A4[m * 16 + k4];
            float4 c = C4[recv * 16 + k4];
            float hx = fmaxf(a.x + c.x, 0.f), hy = fmaxf(a.y + c.y, 0.f);
            float hz = fmaxf(a.z + c.z, 0.f), hw = fmaxf(a.w + c.w, 0.f);
            uint32_t H0 = pkbf(hx, hy), H1 = pkbf(hz, hw);
            uint32_t L0 = pkbf(hx - bf_lo(H0), hy - bf_hi(H0));
            uint32_t L1 = pkbf(hz - bf_lo(H1), hw - bf_hi(H1));
            int widx = (recv * 64 + m) * AHW + 2 * k4;
            *(uint2*)(Ahw + widx) = make_uint2(H0, H1);
            *(uint2*)(Alw + widx) = make_uint2(L0, L1);
        }
    }
    __syncthreads();

    // ---- 3-split bf16 MMA: C[nt][4] = HH + HL + LH ----
    float C[8][4];
#pragma unroll
    for (int nt = 0; nt < 8; nt++)
#pragma unroll
        for (int i = 0; i < 4; i++) C[nt][i] = 0.f;

    int rlw  = w >> 2;
    int row0 = (w & 3) * 16 + g4;
    int abase0 = (rlw * 64 + row0) * AHW;
    int abase1 = abase0 + 8 * AHW;

#pragma unroll
    for (int split = 0; split < 3; split++) {
        const uint32_t* Aw = (split == 2) ? Alw : Ahw;
        int bh = (split == 1) ? 1 : 0;
#pragma unroll
        for (int kt = 0; kt < 4; kt++) {
            int kp = kt * 8 + t4;
            uint32_t a0 = Aw[abase0 + kp];
            uint32_t a1 = Aw[abase1 + kp];
            uint32_t a2 = Aw[abase0 + kp + 4];
            uint32_t a3 = Aw[abase1 + kp + 4];
#pragma unroll
            for (int nt = 0; nt < 8; nt++) {
                const uint32_t* bp = Bs + (((kt * 8 + nt) * 2 + bh) * 32 + lane) * 2;
                uint2 bv = *(const uint2*)bp;
                mma_bf16(C[nt], a0, a1, a2, a3, bv.x, bv.y);
            }
        }
    }

    // ---- epilogue: relu+bias, weight, stage to R (overlays A) ----
    __syncthreads();
    float* R = (float*)smem;               // R[2 recv][64 s][65]
    {
        float wt0 = wts[rlw * 64 + row0 - g4 + g4];   // wts[rlw][row0]
        wt0 = wts[rlw * 64 + row0];
        float wt1 = wts[rlw * 64 + row0 + 8];
#pragma unroll
        for (int nt = 0; nt < 8; nt++) {
            int col = nt * 8 + 2 * t4;
            float bA = b2s[col], bB = b2s[col + 1];
            int ro = (rlw * 64 + row0) * RSTRIDE;
            R[ro + col]                     = wt0 * fmaxf(C[nt][0] + bA, 0.f);
            R[ro + col + 1]                 = wt0 * fmaxf(C[nt][1] + bB, 0.f);
            R[ro + 8 * RSTRIDE + col]       = wt1 * fmaxf(C[nt][2] + bA, 0.f);
            R[ro + 8 * RSTRIDE + col + 1]   = wt1 * fmaxf(C[nt][3] + bB, 0.f);
        }
    }
    __syncthreads();

    // ---- reduce over senders, write per-type message ----
    if (tid < 128) {
        int rl = tid >> 6, j = tid & 63;
        float acc = 0.f;
#pragma unroll
        for (int s = 0; s < NAG; s++)
            acc += R[(rl * 64 + s) * RSTRIDE + j];
        int r = rp * 2 + rl;
        g_msgT[(((long)t * BATCH + b) * NAG + r) * HDIM + j] = acc;
    }
}

// ---------------- K3: node decoder ----------------
__global__ __launch_bounds__(64) void k3_decode(
    const float* __restrict__ x,
    const float* __restrict__ ndw1, const float* __restrict__ ndb1,
    const float* __restrict__ ndw2, const float* __restrict__ ndb2,
    float* __restrict__ out)
{
    int bn = blockIdx.x;
    int j  = threadIdx.x;
    __shared__ float xs[DN];
    __shared__ float ms[HDIM];
    __shared__ float hs[HDIM];

    if (j < DN) xs[j] = x[bn * DN + j];
    ms[j] = g_msgT[(long)bn * HDIM + j] +
            g_msgT[(long)(BATCH * NAG + bn) * HDIM + j];
    __syncthreads();

    float h = ndb1[j];
#pragma unroll
    for (int i = 0; i < DN; i++)   h = fmaf(xs[i], ndw1[i * HDIM + j], h);
#pragma unroll
    for (int k = 0; k < HDIM; k++) h = fmaf(ms[k], ndw1[(DN + k) * HDIM + j], h);
    hs[j] = fmaxf(h, 0.f);
    __syncthreads();

    if (j < DOUT) {
        float o = ndb2[j];
#pragma unroll
        for (int k = 0; k < HDIM; k++) o = fmaf(hs[k], ndw2[k * DOUT + j], o);
        out[bn * DOUT + j] = fmaxf(o, 0.f);
    }
}

extern "C" void kernel_launch(void* const* d_in, const int* in_sizes, int n_in,
                              void* d_out, int out_size)
{
    const float* node_states = (const float*)d_in[0];
    const float* edge_types  = (const float*)d_in[1];
    const float* e0_w1 = (const float*)d_in[2];
    const float* e0_b1 = (const float*)d_in[3];
    const float* e0_w2 = (const float*)d_in[4];
    const float* e0_b2 = (const float*)d_in[5];
    const float* e1_w1 = (const float*)d_in[6];
    const float* e1_b1 = (const float*)d_in[7];
    const float* e1_w2 = (const float*)d_in[8];
    const float* e1_b2 = (const float*)d_in[9];
    const float* nd_w1 = (const float*)d_in[10];
    const float* nd_b1 = (const float*)d_in[11];
    const float* nd_w2 = (const float*)d_in[12];
    const float* nd_b2 = (const float*)d_in[13];
    float* out = (float*)d_out;

    static int smem_set = 0;
    if (!smem_set) {
        cudaFuncSetAttribute(k2_mma, cudaFuncAttributeMaxDynamicSharedMemorySize, SM_TOT);
        smem_set = 1;
    }

    k0_bfrag<<<64, 64>>>(e0_w2, e1_w2);
    k1_precompute<<<BATCH * NAG, 64>>>(node_states, e0_w1, e0_b1, e1_w1, e1_b1);
    k2_mma<<<BATCH * 2 * 32, 256, SM_TOT>>>(edge_types, e0_b2, e1_b2);
    k3_decode<<<BATCH * NAG, 64>>>(node_states, nd_w1, nd_b1, nd_w2, nd_b2, out);
}

// round 10
// speedup vs baseline: 2.0789x; 1.9045x over previous
#include <cuda_runtime.h>
#include <cstdint>

#define BATCH 128
#define NAG   64
#define NEDGE 4032
#define DN    16
#define HDIM  64
#define DOUT  16

// ---------------- scratch (no cudaMalloc) ----------------
__device__ float g_A0[BATCH * NAG * HDIM];
__device__ float g_C0[BATCH * NAG * HDIM];
__device__ float g_A1[BATCH * NAG * HDIM];
__device__ float g_C1[BATCH * NAG * HDIM];
__device__ float g_msgT[2 * BATCH * NAG * HDIM];
// W2 A-operand fragments: [t][jt(4)][kt(4)][hl(2)][lane(32)][4] u32 (bf16x2)
__device__ uint32_t g_Wf[2 * 4 * 4 * 2 * 32 * 4];

// ---------------- helpers ----------------
__device__ __forceinline__ uint32_t pkbf(float lok, float hik) {
    uint32_t d;
    asm("cvt.rn.bf16x2.f32 %0, %1, %2;" : "=r"(d) : "f"(hik), "f"(lok));
    return d;
}
__device__ __forceinline__ float bf_lo(uint32_t u) { return __uint_as_float(u << 16); }
__device__ __forceinline__ float bf_hi(uint32_t u) { return __uint_as_float(u & 0xffff0000u); }

__device__ __forceinline__ void mma_bf16(float c[4], uint4 a, uint2 b) {
    asm volatile(
        "mma.sync.aligned.m16n8k16.row.col.f32.bf16.bf16.f32 "
        "{%0,%1,%2,%3}, {%4,%5,%6,%7}, {%8,%9}, {%0,%1,%2,%3};"
        : "+f"(c[0]), "+f"(c[1]), "+f"(c[2]), "+f"(c[3])
        : "r"(a.x), "r"(a.y), "r"(a.z), "r"(a.w), "r"(b.x), "r"(b.y));
}

#define HSTRIDE 68   /* words per H fragment tile (64 + pad) */

// ---------------- K0: W2 -> bf16 hi/lo A-operand fragments ----------------
// a0={W2[K0,J],W2[K0+1,J]}, a1: J+8, a2: K0+8, a3: J+8,K0+8 ; K0=kt*16+2*t4, J=jt*16+g4
__global__ __launch_bounds__(64) void k0_wfrag(
    const float* __restrict__ e0w2, const float* __restrict__ e1w2)
{
    int blk = blockIdx.x;              // 0..31 : t*16 + jt*4 + kt
    int t  = blk >> 4;
    int jt = (blk >> 2) & 3;
    int kt = blk & 3;
    int tid = threadIdx.x;
    int hl  = tid >> 5;
    int lane = tid & 31;
    int g4 = lane >> 2, t4 = lane & 3;

    const float* w2t = t ? e1w2 : e0w2;
    int K0 = kt * 16 + 2 * t4;
    int J  = jt * 16 + g4;

    float w00 = w2t[K0 * HDIM + J],       w01 = w2t[(K0 + 1) * HDIM + J];
    float w10 = w2t[K0 * HDIM + J + 8],   w11 = w2t[(K0 + 1) * HDIM + J + 8];
    float w20 = w2t[(K0 + 8) * HDIM + J], w21 = w2t[(K0 + 9) * HDIM + J];
    float w30 = w2t[(K0 + 8) * HDIM + J + 8], w31 = w2t[(K0 + 9) * HDIM + J + 8];

    uint4 H;
    H.x = pkbf(w00, w01); H.y = pkbf(w10, w11);
    H.z = pkbf(w20, w21); H.w = pkbf(w30, w31);
    uint4 V;
    if (hl == 0) V = H;
    else {
        V.x = pkbf(w00 - bf_lo(H.x), w01 - bf_hi(H.x));
        V.y = pkbf(w10 - bf_lo(H.y), w11 - bf_hi(H.y));
        V.z = pkbf(w20 - bf_lo(H.z), w21 - bf_hi(H.z));
        V.w = pkbf(w30 - bf_lo(H.w), w31 - bf_hi(H.w));
    }
    *(uint4*)(g_Wf + ((((size_t)((t * 4 + jt) * 4 + kt) * 2 + hl) * 32 + lane) * 4)) = V;
}

// ---------------- K1: factored layer-1 terms ----------------
__global__ __launch_bounds__(64) void k1_precompute(
    const float* __restrict__ x,
    const float* __restrict__ e0w1, const float* __restrict__ e0b1,
    const float* __restrict__ e1w1, const float* __restrict__ e1b1)
{
    int bn = blockIdx.x;
    int j  = threadIdx.x;
    __shared__ float xs[DN];
    if (j < DN) xs[j] = x[bn * DN + j];
    __syncthreads();

    float a0 = 0.f, a1 = 0.f, c0 = e0b1[j], c1 = e1b1[j];
#pragma unroll
    for (int i = 0; i < DN; i++) {
        float xv = xs[i];
        a0 += xv * e0w1[i * HDIM + j];
        c0 += xv * e0w1[(DN + i) * HDIM + j];
        a1 += xv * e1w1[i * HDIM + j];
        c1 += xv * e1w1[(DN + i) * HDIM + j];
    }
    g_A0[bn * HDIM + j] = a0;
    g_C0[bn * HDIM + j] = c0;
    g_A1[bn * HDIM + j] = a1;
    g_C1[bn * HDIM + j] = c1;
}

// ---------------- K2: 3-split bf16 mma, W in regs (A-op), H in smem (B-op) ----------
// block = (b, type, recv-pair), 256 thr = 8 warps: warp = (rl = w>>2, jt = w&3).
// D'[j,s] = sum_k W2[k,j] * H[s,k];  msg[j] = sum_s wt[s]*relu(D'+b2[j])
__global__ __launch_bounds__(256, 2) void k2_mma(
    const float* __restrict__ etypes,
    const float* __restrict__ e0b2, const float* __restrict__ e1b2)
{
    __shared__ uint32_t Hw[128 * HSTRIDE];   // [recv][hl][kt][st] tiles of 64+4 words
    __shared__ float cbuf[2][HDIM];
    __shared__ float wts[2][NAG];
    __shared__ float b2s[HDIM];

    int blk = blockIdx.x;                 // BATCH * 2 * 32
    int rp  = blk & 31;
    int t   = (blk >> 5) & 1;
    int b   = blk >> 6;
    int tid = threadIdx.x;
    int w   = tid >> 5;
    int lane = tid & 31;
    int g4  = lane >> 2, t4 = lane & 3;

    const float* At  = (t ? g_A1 : g_A0) + (long)(b * NAG) * HDIM;
    const float* Ct  = (t ? g_C1 : g_C0) + (long)(b * NAG) * HDIM;
    const float* b2t = t ? e1b2 : e0b2;

    int rl = w >> 2, jt = w & 3;

    // preload W-hi fragments for this warp's j-tile (16 regs), L2-hot
    uint4 WH[4];
#pragma unroll
    for (int kt = 0; kt < 4; kt++)
        WH[kt] = *(const uint4*)(g_Wf +
            ((((size_t)((t * 4 + jt) * 4 + kt) * 2 + 0) * 32 + lane) * 4));

    // small loads: C rows (2 recv), edge weights, bias
    if (tid < 128) {
        int rr = tid >> 6, k = tid & 63;
        int r  = rp * 2 + rr;
        cbuf[rr][k] = Ct[r * HDIM + k];
        int s = k;
        float wt = 0.f;
        if (s != r) {
            int e = s * 63 + r - (r > s ? 1 : 0);   // np.where(ones-eye) ordering
            wt = etypes[((long)b * NEDGE + e) * 3 + 1 + t];
        }
        wts[rr][s] = wt;
    } else if (tid < 192) {
        b2s[tid - 128] = b2t[tid - 128];
    }
    __syncthreads();

    // ---- build H fragments (hi/lo) for both receivers; A read ONCE ----
    {
        const float4* A4 = (const float4*)At;
        const float4* C4 = (const float4*)cbuf;
        float4 av[4];
#pragma unroll
        for (int it = 0; it < 4; it++) av[it] = A4[it * 256 + tid];
#pragma unroll
        for (int it = 0; it < 4; it++) {
            int idx = it * 256 + tid;          // s = idx>>4 (0..63), q = idx&15
            int s = idx >> 4, q = idx & 15;
            int kt = q >> 2;
            int lp = (q & 1) * 2;              // lane k-part
            int rr = (q >> 1) & 1;             // reg index (b0/b1)
            int st = s >> 3;
            int lb = lp + (s & 7) * 4;         // lane base
            float4 a = av[it];
#pragma unroll
            for (int recv = 0; recv < 2; recv++) {
                float4 c = C4[recv * 16 + q];
                float h0 = fmaxf(a.x + c.x, 0.f), h1 = fmaxf(a.y + c.y, 0.f);
                float h2 = fmaxf(a.z + c.z, 0.f), h3 = fmaxf(a.w + c.w, 0.f);
                uint32_t P0h = pkbf(h0, h1), P1h = pkbf(h2, h3);
                uint32_t P0l = pkbf(h0 - bf_lo(P0h), h1 - bf_hi(P0h));
                uint32_t P1l = pkbf(h2 - bf_lo(P1h), h3 - bf_hi(P1h));
                int bh = (((recv * 2 + 0) * 4 + kt) * 8 + st) * HSTRIDE;
                int bl = (((recv * 2 + 1) * 4 + kt) * 8 + st) * HSTRIDE;
                Hw[bh + lb * 2 + rr]       = P0h;
                Hw[bh + (lb + 1) * 2 + rr] = P1h;
                Hw[bl + lb * 2 + rr]       = P0l;
                Hw[bl + (lb + 1) * 2 + rr] = P1l;
            }
        }
    }
    __syncthreads();

    // ---- MMA: per warp 96 HMMA, 64 LDS.64, W-lo loaded per kt ----
    float C[8][4];
#pragma unroll
    for (int st = 0; st < 8; st++)
#pragma unroll
        for (int i = 0; i < 4; i++) C[st][i] = 0.f;

    int hb0 = ((rl * 2 + 0) * 4) * 8 * HSTRIDE;   // hi plane base for this recv
    int hb1 = ((rl * 2 + 1) * 4) * 8 * HSTRIDE;   // lo plane base

#pragma unroll
    for (int kt = 0; kt < 4; kt++) {
        uint4 wh = WH[kt];
        uint4 wl = *(const uint4*)(g_Wf +
            ((((size_t)((t * 4 + jt) * 4 + kt) * 2 + 1) * 32 + lane) * 4));
        int kbh = hb0 + kt * 8 * HSTRIDE;
        int kbl = hb1 + kt * 8 * HSTRIDE;
#pragma unroll
        for (int sp = 0; sp < 8; sp += 2) {
            uint2 h0h = *(const uint2*)(Hw + kbh + sp * HSTRIDE + lane * 2);
            uint2 h1h = *(const uint2*)(Hw + kbh + (sp + 1) * HSTRIDE + lane * 2);
            uint2 h0l = *(const uint2*)(Hw + kbl + sp * HSTRIDE + lane * 2);
            uint2 h1l = *(const uint2*)(Hw + kbl + (sp + 1) * HSTRIDE + lane * 2);
            mma_bf16(C[sp],     wh, h0h);
            mma_bf16(C[sp + 1], wh, h1h);
            mma_bf16(C[sp],     wh, h0l);
            mma_bf16(C[sp + 1], wh, h1l);
            mma_bf16(C[sp],     wl, h0h);
            mma_bf16(C[sp + 1], wl, h1h);
        }
    }

    // ---- register epilogue: msg[j] = sum_s wt[s]*relu(D+b2[j]) ----
    {
        int j0 = jt * 16 + g4, j1 = j0 + 8;
        float b2a = b2s[j0], b2b = b2s[j1];
        float aJ0 = 0.f, aJ1 = 0.f;
#pragma unroll
        for (int st = 0; st < 8; st++) {
            int s0 = st * 8 + 2 * t4;
            float2 wv = *(const float2*)&wts[rl][s0];
            aJ0 += wv.x * fmaxf(C[st][0] + b2a, 0.f)
                 + wv.y * fmaxf(C[st][1] + b2a, 0.f);
            aJ1 += wv.x * fmaxf(C[st][2] + b2b, 0.f)
                 + wv.y * fmaxf(C[st][3] + b2b, 0.f);
        }
        aJ0 += __shfl_xor_sync(0xffffffffu, aJ0, 1);
        aJ0 += __shfl_xor_sync(0xffffffffu, aJ0, 2);
        aJ1 += __shfl_xor_sync(0xffffffffu, aJ1, 1);
        aJ1 += __shfl_xor_sync(0xffffffffu, aJ1, 2);
        if (t4 == 0) {
            int r = rp * 2 + rl;
            float* dst = g_msgT + (((long)t * BATCH + b) * NAG + r) * HDIM;
            dst[j0] = aJ0;
            dst[j1] = aJ1;
        }
    }
}

// ---------------- K3: node decoder, 4 nodes/block, smem-cached weights --------
__global__ __launch_bounds__(256) void k3_decode(
    const float* __restrict__ x,
    const float* __restrict__ ndw1, const float* __restrict__ ndb1,
    const float* __restrict__ ndw2, const float* __restrict__ ndb2,
    float* __restrict__ out)
{
    __shared__ float w1s[(DN + HDIM) * HDIM];   // 80*64 = 20 KB
    __shared__ float w2s[HDIM * DOUT];          // 4 KB
    __shared__ float xs[4][DN];
    __shared__ float ms[4][HDIM];
    __shared__ float hs[4][HDIM];

    int tid  = threadIdx.x;
    int node = tid >> 6;
    int j    = tid & 63;
    int bn   = blockIdx.x * 4 + node;

#pragma unroll
    for (int i = 0; i < 20; i++) w1s[i * 256 + tid] = ndw1[i * 256 + tid];
#pragma unroll
    for (int i = 0; i < 4; i++)  w2s[i * 256 + tid] = ndw2[i * 256 + tid];

    if (j < DN) xs[node][j] = x[bn * DN + j];
    ms[node][j] = g_msgT[(long)bn * HDIM + j] +
                  g_msgT[(long)(BATCH * NAG + bn) * HDIM + j];
    __syncthreads();

    float h = ndb1[j];
#pragma unroll
    for (int i = 0; i < DN; i++)   h = fmaf(xs[node][i], w1s[i * HDIM + j], h);
#pragma unroll
    for (int k = 0; k < HDIM; k++) h = fmaf(ms[node][k], w1s[(DN + k) * HDIM + j], h);
    hs[node][j] = fmaxf(h, 0.f);
    __syncthreads();

    if (j < DOUT) {
        float o = ndb2[j];
#pragma unroll
        for (int k = 0; k < HDIM; k++) o = fmaf(hs[node][k], w2s[k * DOUT + j], o);
        out[bn * DOUT + j] = fmaxf(o, 0.f);
    }
}

extern "C" void kernel_launch(void* const* d_in, const int* in_sizes, int n_in,
                              void* d_out, int out_size)
{
    const float* node_states = (const float*)d_in[0];
    const float* edge_types  = (const float*)d_in[1];
    const float* e0_w1 = (const float*)d_in[2];
    const float* e0_b1 = (const float*)d_in[3];
    const float* e0_w2 = (const float*)d_in[4];
    const float* e0_b2 = (const float*)d_in[5];
    const float* e1_w1 = (const float*)d_in[6];
    const float* e1_b1 = (const float*)d_in[7];
    const float* e1_w2 = (const float*)d_in[8];
    const float* e1_b2 = (const float*)d_in[9];
    const float* nd_w1 = (const float*)d_in[10];
    const float* nd_b1 = (const float*)d_in[11];
    const float* nd_w2 = (const float*)d_in[12];
    const float* nd_b2 = (const float*)d_in[13];
    float* out = (float*)d_out;

    k0_wfrag<<<32, 64>>>(e0_w2, e1_w2);
    k1_precompute<<<BATCH * NAG, 64>>>(node_states, e0_w1, e0_b1, e1_w1, e1_b1);
    k2_mma<<<BATCH * 2 * 32, 256>>>(edge_types, e0_b2, e1_b2);
    k3_decode<<<BATCH * NAG / 4, 256>>>(node_states, nd_w1, nd_b1, nd_w2, nd_b2, out);
}